// round 11
// baseline (speedup 1.0000x reference)
#include <cuda_runtime.h>
#include <cuda_bf16.h>
#include <cstdint>

#define NPTS 65536
#define HID  256
#define SLICE ((size_t)NPTS * HID)
#define NCH  13
#define NSG  (NPTS / 128)     // 512 sample groups

// fp32 GEMM-output buffers and bf16 hi/lo split activation buffers
static __device__ float          g_C  [(size_t)NCH * NPTS * HID];
static __device__ float          g_Cd [(size_t)3 * NPTS * HID];
static __device__ __nv_bfloat16  g_hiA[(size_t)NCH * NPTS * HID];
static __device__ __nv_bfloat16  g_loA[(size_t)NCH * NPTS * HID];
static __device__ __nv_bfloat16  g_hiB[(size_t)NCH * NPTS * HID];
static __device__ __nv_bfloat16  g_loB[(size_t)NCH * NPTS * HID];
// weight splits: slot 0=W2, 1=W3, 2=Wp1, 3=Wd1
static __device__ __nv_bfloat16  g_Whi[4 * 256 * 256];
static __device__ __nv_bfloat16  g_Wlo[4 * 256 * 256];
// group-completion counters (BSS zero; head_reduce resets each replay)
static __device__ int            g_cnt[NSG];

// ---------------------------------------------------------------------------
// hi = truncate-to-bf16(f), lo = RN-bf16(f - hi)
// ---------------------------------------------------------------------------
__device__ __forceinline__ void store_hl(__nv_bfloat16* __restrict__ hi,
                                         __nv_bfloat16* __restrict__ lo,
                                         size_t idx, float f) {
    unsigned u = __float_as_uint(f);
    float h = __uint_as_float(u & 0xFFFF0000u);
    hi[idx] = __ushort_as_bfloat16((unsigned short)(u >> 16));
    lo[idx] = __float2bfloat16(f - h);
}

__device__ __forceinline__ __nv_bfloat16 trunc_bf(float f) {
    return __ushort_as_bfloat16((unsigned short)(__float_as_uint(f) >> 16));
}
__device__ __forceinline__ float trunc_res(float f) {
    return f - __uint_as_float(__float_as_uint(f) & 0xFFFF0000u);
}

__global__ void wconv_kernel(const float* __restrict__ w2,
                             const float* __restrict__ w3,
                             const float* __restrict__ wp1,
                             const float* __restrict__ wd1) {
    int e = blockIdx.x * blockDim.x + threadIdx.x;
    if (e >= 4 * 65536) return;
    int m = e >> 16;
    int l = e & 65535;
    const float* src = (m == 0) ? w2 : (m == 1) ? w3 : (m == 2) ? wp1 : wd1;
    store_hl(g_Whi, g_Wlo, (size_t)e, src[l]);
}

__global__ void layer1_kernel(const float* __restrict__ x,
                              const float* __restrict__ y,
                              const float* __restrict__ t,
                              const float* __restrict__ W1,
                              const float* __restrict__ b1) {
    int e = blockIdx.x * blockDim.x + threadIdx.x;
    if (e >= NPTS * HID) return;
    int n = e >> 8;
    int k = e & 255;
    float cx = W1[k * 3 + 0];
    float cy = W1[k * 3 + 1];
    float ct = W1[k * 3 + 2];
    float z = cx * x[n] + cy * y[n] + ct * t[n] + b1[k];
    float h = tanhf(z);
    float d = 1.0f - h * h;
    const size_t S = SLICE;
    store_hl(g_hiA, g_loA, e, h);
    store_hl(g_hiA, g_loA, S * 1 + e, d * cx);
    store_hl(g_hiA, g_loA, S * 2 + e, d * cy);
    store_hl(g_hiA, g_loA, S * 3 + e, d * ct);
    float m2 = -2.0f * h * d;
    store_hl(g_hiA, g_loA, S * 4 + e, m2 * cx * cx);
    store_hl(g_hiA, g_loA, S * 5 + e, m2 * cx * cy);
    store_hl(g_hiA, g_loA, S * 6 + e, m2 * cy * cy);
    store_hl(g_hiA, g_loA, S * 7 + e, m2 * cx * ct);
    store_hl(g_hiA, g_loA, S * 8 + e, m2 * cy * ct);
    float m3 = d * (6.0f * h * h - 2.0f);
    store_hl(g_hiA, g_loA, S * 9 + e,  m3 * cx * cx * cx);
    store_hl(g_hiA, g_loA, S * 10 + e, m3 * cx * cx * cy);
    store_hl(g_hiA, g_loA, S * 11 + e, m3 * cx * cy * cy);
    store_hl(g_hiA, g_loA, S * 12 + e, m3 * cy * cy * cy);
}

// ---------------------------------------------------------------------------
// Tensor-core GEMM (NT), C[m,n] = sum_k A[m,k]*W[n,k], K = N = 256.
// Block tile 128x128, 8 warps (32x64 warp tile), K-chunk 32.
// 3-stage cp.async ring, one __syncthreads per chunk; XOR-swizzled smem.
// Accum Ah*Wh + Ah*Wl + Al*Wh (fp32).
// fuse!=0: 1-D grid; bx -> sgrp = bx/26, j = bx%26, ch = j%13, nhalf = j/13.
//   The 26 blocks of a group are CONTIGUOUS in bx (deadlock-safe dispatch).
//   After the epilogue all 26 arrive on g_cnt[sgrp], spin to `target`, then
//   each computes its own 1/26 slice of the tanh-jet combine (uniform work).
// fuse==0: 2-D grid (bx, by); blocks >= nbig run the appended data-head job.
// ---------------------------------------------------------------------------
#define STGB  32768            // per-stage bytes: A 16K + W 16K
#define SMSZ  (3 * STGB)       // 98304

#define LDSM4(R, addr) \
    asm volatile("ldmatrix.sync.aligned.m8n8.x4.shared.b16 {%0,%1,%2,%3}, [%4];" \
                 : "=r"((R)[0]), "=r"((R)[1]), "=r"((R)[2]), "=r"((R)[3]) \
                 : "r"(addr))
#define CPA(dst, src) \
    asm volatile("cp.async.cg.shared.global [%0], [%1], 16;" :: "r"(dst), "l"(src))
#define CPC() asm volatile("cp.async.commit_group;")
#define CPW1() asm volatile("cp.async.wait_group 1;" ::: "memory")
#define CPW0() asm volatile("cp.async.wait_group 0;" ::: "memory")

__device__ __forceinline__ void mma_bf16(float* c, const unsigned* a,
                                         unsigned b0, unsigned b1) {
    asm volatile(
        "mma.sync.aligned.m16n8k16.row.col.f32.bf16.bf16.f32 "
        "{%0,%1,%2,%3}, {%4,%5,%6,%7}, {%8,%9}, {%0,%1,%2,%3};"
        : "+f"(c[0]), "+f"(c[1]), "+f"(c[2]), "+f"(c[3])
        : "r"(a[0]), "r"(a[1]), "r"(a[2]), "r"(a[3]), "r"(b0), "r"(b1));
}

__global__ void __launch_bounds__(256, 2)
gemm_v11(const __nv_bfloat16* __restrict__ Ahi,
         const __nv_bfloat16* __restrict__ Alo,
         const __nv_bfloat16* Whi_, const __nv_bfloat16* Wlo_, float* C_,
         const __nv_bfloat16* Whi2_, const __nv_bfloat16* Wlo2_, float* C2_,
         int nbig, int fuse, int target,
         const float* __restrict__ bvec,
         __nv_bfloat16* __restrict__ hiO,
         __nv_bfloat16* __restrict__ loO) {
    extern __shared__ __align__(128) unsigned char sm[];
    const unsigned sb = (unsigned)__cvta_generic_to_shared(sm);

    int bx = blockIdx.x;
    const __nv_bfloat16* Whi = Whi_;
    const __nv_bfloat16* Wlo = Wlo_;
    float* C = C_;
    int sgrp = 0, j26 = 0;
    size_t blockRow;
    int blockN;
    if (fuse) {
        sgrp = bx / 26;
        j26  = bx - sgrp * 26;
        int ch = j26 % 13;
        blockRow = (size_t)ch * NPTS + (size_t)sgrp * 128;
        blockN   = (j26 / 13) * 128;
    } else {
        if (bx >= nbig) {            // appended second job (data head)
            bx -= nbig;
            Whi = Whi2_;
            Wlo = Wlo2_;
            C = C2_;
        }
        blockRow = (size_t)bx * 128;
        blockN   = blockIdx.y * 128;
    }

    const int tid  = threadIdx.x;
    const int lane = tid & 31;
    const int warp = tid >> 5;
    const int wm   = (warp & 3) * 32;
    const int wn   = (warp >> 2) * 64;

    // loader: 2 threads per row; each covers 2 hi chunks + 2 lo chunks per array
    const int lr = tid >> 1;          // row 0..127
    const int lc = (tid & 1) * 2;     // hi chunk base 0 or 2
    const unsigned sw = (unsigned)(lr & 7);
    const __nv_bfloat16* gAh = Ahi + (blockRow + lr) * 256;
    const __nv_bfloat16* gAl = Alo + (blockRow + lr) * 256;
    const __nv_bfloat16* gWh = Whi + (size_t)(blockN + lr) * 256;
    const __nv_bfloat16* gWl = Wlo + (size_t)(blockN + lr) * 256;
    const unsigned aDst = sb + lr * 128;
    const unsigned wDst = sb + 16384 + lr * 128;

    float acc[2][8][4];
#pragma unroll
    for (int i = 0; i < 2; i++)
#pragma unroll
        for (int j = 0; j < 8; j++)
#pragma unroll
            for (int l = 0; l < 4; l++) acc[i][j][l] = 0.0f;

#define ISSUE(kc) do {                                                         \
        const int _s = (kc) % 3;                                               \
        const int _ko = (kc) * 32;                                             \
        unsigned _a = aDst + _s * STGB;                                        \
        unsigned _w = wDst + _s * STGB;                                        \
        CPA(_a + ((unsigned)((lc    ) ^ sw) << 4), gAh + _ko + lc * 8);        \
        CPA(_a + ((unsigned)((lc + 1) ^ sw) << 4), gAh + _ko + lc * 8 + 8);    \
        CPA(_a + ((unsigned)((lc + 4) ^ sw) << 4), gAl + _ko + lc * 8);        \
        CPA(_a + ((unsigned)((lc + 5) ^ sw) << 4), gAl + _ko + lc * 8 + 8);    \
        CPA(_w + ((unsigned)((lc    ) ^ sw) << 4), gWh + _ko + lc * 8);        \
        CPA(_w + ((unsigned)((lc + 1) ^ sw) << 4), gWh + _ko + lc * 8 + 8);    \
        CPA(_w + ((unsigned)((lc + 4) ^ sw) << 4), gWl + _ko + lc * 8);        \
        CPA(_w + ((unsigned)((lc + 5) ^ sw) << 4), gWl + _ko + lc * 8 + 8);    \
        CPC();                                                                 \
    } while (0)

    ISSUE(0);
    ISSUE(1);

    // fragment address components
    const int arow  = wm + (lane & 15);                      // + mt*16
    const int acsel = lane >> 4;                             // 0/1
    const int brow  = wn + (lane & 7) + ((lane >> 4) << 3);  // + ng*16
    const int bcsel = (lane >> 3) & 1;

#pragma unroll 1
    for (int kc = 0; kc < 8; kc++) {
        if (kc < 7) { CPW1(); } else { CPW0(); }
        __syncthreads();
        if (kc < 6) ISSUE(kc + 2);          // safe: that stage was read at kc-1

        const unsigned s0 = sb + (kc % 3) * STGB;
#pragma unroll
        for (int step = 0; step < 2; step++) {
            unsigned aH[2][4], aL[2][4];
            const int cA = step * 2 + acsel;
#pragma unroll
            for (int mt = 0; mt < 2; mt++) {
                const int row = arow + mt * 16;
                const unsigned rs = (unsigned)(row & 7);
                const unsigned ab = s0 + row * 128;
                LDSM4(aH[mt], ab + ((unsigned)(cA ^ rs) << 4));
                LDSM4(aL[mt], ab + ((unsigned)((cA + 4) ^ rs) << 4));
            }
            const int cB = step * 2 + bcsel;
#pragma unroll
            for (int ng = 0; ng < 4; ng++) {
                const int rowb = brow + ng * 16;
                const unsigned rbs = (unsigned)(rowb & 7);
                const unsigned bb = s0 + 16384 + rowb * 128;
                unsigned bh[4], bl[4];
                LDSM4(bh, bb + ((unsigned)(cB ^ rbs) << 4));
                LDSM4(bl, bb + ((unsigned)((cB + 4) ^ rbs) << 4));
#pragma unroll
                for (int mt = 0; mt < 2; mt++) {
                    mma_bf16(acc[mt][2 * ng],     aH[mt], bh[0], bh[1]);
                    mma_bf16(acc[mt][2 * ng],     aH[mt], bl[0], bl[1]);
                    mma_bf16(acc[mt][2 * ng],     aL[mt], bh[0], bh[1]);
                    mma_bf16(acc[mt][2 * ng + 1], aH[mt], bh[2], bh[3]);
                    mma_bf16(acc[mt][2 * ng + 1], aH[mt], bl[2], bl[3]);
                    mma_bf16(acc[mt][2 * ng + 1], aL[mt], bh[2], bh[3]);
                }
            }
        }
    }

    // epilogue
    const int g  = lane >> 2;
    const int t4 = lane & 3;
#pragma unroll
    for (int mt = 0; mt < 2; mt++) {
        size_t row = blockRow + wm + mt * 16 + g;
#pragma unroll
        for (int nt = 0; nt < 8; nt++) {
            int col = blockN + wn + nt * 8 + t4 * 2;
            *(float2*)(C + row * 256 + col) =
                make_float2(acc[mt][nt][0], acc[mt][nt][1]);
            *(float2*)(C + (row + 8) * 256 + col) =
                make_float2(acc[mt][nt][2], acc[mt][nt][3]);
        }
    }

    if (!fuse) return;

    // ---- group barrier: all 26 (contiguous-bx) blocks arrive, then slice ----
    __threadfence();                       // release this block's C writes
    __syncthreads();                       // all threads' stores+fences done
    if (tid == 0) {
        atomicAdd(&g_cnt[sgrp], 1);
        int v;
        do {
            asm volatile("ld.acquire.gpu.global.s32 %0, [%1];"
                         : "=r"(v) : "l"(&g_cnt[sgrp]) : "memory");
            if (v >= target) break;
            __nanosleep(64);
        } while (true);
    }
    __syncthreads();
    __threadfence();                       // acquire peers' C writes

    // slice of 8192 quads (128 samples * 64 quads), uniform across 26 blocks
    const int qlo = (j26 * 8192) / 26;
    const int qhi = ((j26 + 1) * 8192) / 26;
    const size_t S4 = SLICE / 4;
    const size_t base4 = (size_t)sgrp * 8192;

#pragma unroll 1
    for (int q = qlo + tid; q < qhi; q += 256) {
        size_t e4 = base4 + q;
        const int kb = (q & 63) * 4;

        float4 zq[13];
#pragma unroll
        for (int ch = 0; ch < 13; ch++)
            zq[ch] = ((const float4*)C)[ch * S4 + e4];

        float o[13][4];
#pragma unroll
        for (int jj = 0; jj < 4; jj++) {
            float zh = ((const float*)&zq[0])[jj] + bvec[kb + jj];
            float zx = ((const float*)&zq[1])[jj],  zy = ((const float*)&zq[2])[jj];
            float zt = ((const float*)&zq[3])[jj];
            float zxx = ((const float*)&zq[4])[jj], zxy = ((const float*)&zq[5])[jj];
            float zyy = ((const float*)&zq[6])[jj], zxt = ((const float*)&zq[7])[jj];
            float zyt = ((const float*)&zq[8])[jj];
            float zxxx = ((const float*)&zq[9])[jj],  zxxy = ((const float*)&zq[10])[jj];
            float zxyy = ((const float*)&zq[11])[jj], zyyy = ((const float*)&zq[12])[jj];

            float h = tanhf(zh);
            float d = 1.0f - h * h;
            float hd2 = -2.0f * h * d;
            float c3 = (4.0f * h * h - 2.0f * d) * d;

            o[0][jj] = h;
            o[1][jj] = d * zx;
            o[2][jj] = d * zy;
            o[3][jj] = d * zt;
            o[4][jj] = d * zxx + hd2 * zx * zx;
            o[5][jj] = d * zxy + hd2 * zx * zy;
            o[6][jj] = d * zyy + hd2 * zy * zy;
            o[7][jj] = d * zxt + hd2 * zx * zt;
            o[8][jj] = d * zyt + hd2 * zy * zt;
            o[9][jj]  = d * zxxx + hd2 * 3.0f * zx * zxx + c3 * zx * zx * zx;
            o[10][jj] = d * zxxy + hd2 * (zy * zxx + 2.0f * zx * zxy) + c3 * zx * zx * zy;
            o[11][jj] = d * zxyy + hd2 * (2.0f * zy * zxy + zx * zyy) + c3 * zx * zy * zy;
            o[12][jj] = d * zyyy + hd2 * 3.0f * zy * zyy + c3 * zy * zy * zy;
        }

#pragma unroll
        for (int ch = 0; ch < 13; ch++) {
            __nv_bfloat162 h0, h1, l0, l1;
            h0.x = trunc_bf(o[ch][0]); h0.y = trunc_bf(o[ch][1]);
            h1.x = trunc_bf(o[ch][2]); h1.y = trunc_bf(o[ch][3]);
            l0.x = __float2bfloat16(trunc_res(o[ch][0]));
            l0.y = __float2bfloat16(trunc_res(o[ch][1]));
            l1.x = __float2bfloat16(trunc_res(o[ch][2]));
            l1.y = __float2bfloat16(trunc_res(o[ch][3]));
            ((__nv_bfloat162*)hiO)[ch * (S4 * 2) + e4 * 2]     = h0;
            ((__nv_bfloat162*)hiO)[ch * (S4 * 2) + e4 * 2 + 1] = h1;
            ((__nv_bfloat162*)loO)[ch * (S4 * 2) + e4 * 2]     = l0;
            ((__nv_bfloat162*)loO)[ch * (S4 * 2) + e4 * 2 + 1] = l1;
        }
    }
}

// ---------------------------------------------------------------------------
// Merged head reduction (+ counter reset for graph replay).
// Blocks [0, NPTS/8): PDE head on Z (13ch); [NPTS/8, 2*NPTS/8): data head.
// ---------------------------------------------------------------------------
__global__ void head_reduce(const float* __restrict__ Z,
                            const float* __restrict__ Zd,
                            const float* __restrict__ bp1,
                            const float* __restrict__ Wp2,
                            const float* __restrict__ lam1p,
                            const float* __restrict__ lam2p,
                            const float* __restrict__ bd1,
                            const float* __restrict__ Wd2,
                            const float* __restrict__ bd2,
                            float* __restrict__ out) {
    const int NB = NPTS / 8;
    const int lane = threadIdx.x & 31;
    const size_t S = SLICE;

    if (blockIdx.x == 0) {          // reset fusion counters for next replay
        if (threadIdx.x < 256) {
            g_cnt[threadIdx.x] = 0;
            g_cnt[threadIdx.x + 256] = 0;
        }
    }

    if (blockIdx.x < NB) {
        int warp = (blockIdx.x * blockDim.x + threadIdx.x) >> 5;
        const size_t base = (size_t)warp * 256;

        float acc[14];
#pragma unroll
        for (int i = 0; i < 14; i++) acc[i] = 0.0f;

#pragma unroll
        for (int kk = lane; kk < 256; kk += 32) {
            size_t e = base + kk;
            float zh = Z[e] + bp1[kk];
            float h = tanhf(zh);
            float d = 1.0f - h * h;
            float zx = Z[S + e], zy = Z[2 * S + e], zt = Z[3 * S + e];
            float zxx = Z[4 * S + e], zxy = Z[5 * S + e], zyy = Z[6 * S + e];
            float zxt = Z[7 * S + e], zyt = Z[8 * S + e];
            float zxxx = Z[9 * S + e], zxxy = Z[10 * S + e];
            float zxyy = Z[11 * S + e], zyyy = Z[12 * S + e];
            float hd2 = -2.0f * h * d;
            float c3 = (4.0f * h * h - 2.0f * d) * d;

            float hx = d * zx, hy = d * zy, ht = d * zt;
            float hxx = d * zxx + hd2 * zx * zx;
            float hxy = d * zxy + hd2 * zx * zy;
            float hyy = d * zyy + hd2 * zy * zy;
            float hxt = d * zxt + hd2 * zx * zt;
            float hyt = d * zyt + hd2 * zy * zt;
            float hxxx = d * zxxx + hd2 * 3.0f * zx * zxx + c3 * zx * zx * zx;
            float hxxy = d * zxxy + hd2 * (zy * zxx + 2.0f * zx * zxy) + c3 * zx * zx * zy;
            float hxyy = d * zxyy + hd2 * (2.0f * zy * zxy + zx * zyy) + c3 * zx * zy * zy;
            float hyyy = d * zyyy + hd2 * 3.0f * zy * zyy + c3 * zy * zy * zy;

            float w0 = Wp2[kk];
            float w1 = Wp2[256 + kk];
            acc[0] += w0 * hx;   acc[1] += w0 * hy;   acc[2] += w0 * ht;
            acc[3] += w0 * hxx;  acc[4] += w0 * hxy;  acc[5] += w0 * hyy;
            acc[6] += w0 * hxt;  acc[7] += w0 * hyt;
            acc[8] += w0 * hxxx; acc[9] += w0 * hxxy;
            acc[10] += w0 * hxyy; acc[11] += w0 * hyyy;
            acc[12] += w1 * hx;  acc[13] += w1 * hy;
        }
#pragma unroll
        for (int i = 0; i < 14; i++)
#pragma unroll
            for (int o = 16; o; o >>= 1)
                acc[i] += __shfl_xor_sync(0xffffffffu, acc[i], o);

        if (lane == 0) {
            float lam1 = lam1p[0], lam2 = lam2p[0];
            float sx = acc[0], sy = acc[1];
            float sxx = acc[3], sxy = acc[4], syy = acc[5], sxt = acc[6], syt = acc[7];
            float sxxx = acc[8], sxxy = acc[9], sxyy = acc[10], syyy = acc[11];
            float px = acc[12], py = acc[13];
            float u = sy, v = -sx;
            float f = lam1 * (syt + u * sxy + v * syy) + px - lam2 * (sxxy + syyy);
            float g = lam1 * (-sxt + u * (-sxx) + v * (-sxy)) + py - lam2 * (-sxxx - sxyy);
            out[3 * NPTS + warp] = f;
            out[4 * NPTS + warp] = g;
        }
    } else {
        int warp = ((blockIdx.x - NB) * blockDim.x + threadIdx.x) >> 5;
        const size_t base = (size_t)warp * 256;
        float ap = 0.0f, au = 0.0f, av = 0.0f;
#pragma unroll
        for (int kk = lane; kk < 256; kk += 32) {
            size_t e = base + kk;
            float zh = Zd[e] + bd1[kk];
            float h = tanhf(zh);
            float d = 1.0f - h * h;
            float hx = d * Zd[S + e];
            float hy = d * Zd[2 * S + e];
            float w0 = Wd2[kk];
            float w1 = Wd2[256 + kk];
            ap += w1 * h;
            au += w0 * hy;
            av += w0 * hx;
        }
#pragma unroll
        for (int o = 16; o; o >>= 1) {
            ap += __shfl_xor_sync(0xffffffffu, ap, o);
            au += __shfl_xor_sync(0xffffffffu, au, o);
            av += __shfl_xor_sync(0xffffffffu, av, o);
        }
        if (lane == 0) {
            out[warp] = ap + bd2[1];
            out[NPTS + warp] = au;
            out[2 * NPTS + warp] = -av;
        }
    }
}

// ---------------------------------------------------------------------------
// Host launch
// ---------------------------------------------------------------------------
extern "C" void kernel_launch(void* const* d_in, const int* in_sizes, int n_in,
                              void* d_out, int out_size) {
    const float* x   = (const float*)d_in[0];
    const float* y   = (const float*)d_in[1];
    const float* t   = (const float*)d_in[2];
    const float* W1  = (const float*)d_in[6];
    const float* b1  = (const float*)d_in[7];
    const float* W2  = (const float*)d_in[8];
    const float* b2  = (const float*)d_in[9];
    const float* W3  = (const float*)d_in[10];
    const float* b3  = (const float*)d_in[11];
    const float* Wp1 = (const float*)d_in[12];
    const float* bp1 = (const float*)d_in[13];
    const float* Wp2 = (const float*)d_in[14];
    const float* Wd1 = (const float*)d_in[16];
    const float* bd1 = (const float*)d_in[17];
    const float* Wd2 = (const float*)d_in[18];
    const float* bd2 = (const float*)d_in[19];
    const float* lam1 = (const float*)d_in[20];
    const float* lam2 = (const float*)d_in[21];
    float* out = (float*)d_out;

    float *C = nullptr, *Cd = nullptr;
    __nv_bfloat16 *hiA, *loA, *hiB, *loB, *Whi, *Wlo;
    cudaGetSymbolAddress((void**)&C,   g_C);
    cudaGetSymbolAddress((void**)&Cd,  g_Cd);
    cudaGetSymbolAddress((void**)&hiA, g_hiA);
    cudaGetSymbolAddress((void**)&loA, g_loA);
    cudaGetSymbolAddress((void**)&hiB, g_hiB);
    cudaGetSymbolAddress((void**)&loB, g_loB);
    cudaGetSymbolAddress((void**)&Whi, g_Whi);
    cudaGetSymbolAddress((void**)&Wlo, g_Wlo);

    static bool attr_set = false;
    if (!attr_set) {
        cudaFuncSetAttribute(gemm_v11, cudaFuncAttributeMaxDynamicSharedMemorySize, SMSZ);
        attr_set = true;
    }

    const int NH = NPTS * HID;
    const int M13_T = NCH * NPTS / 128;   // 6656
    const int M3_T  = 3 * NPTS / 128;     // 1536
    const int WOFF = 256 * 256;

    wconv_kernel<<<(4 * 65536) / 256, 256>>>(W2, W3, Wp1, Wd1);
    layer1_kernel<<<NH / 256, 256>>>(x, y, t, W1, b1);

    // Layer 2: 1-D fused GEMM + combine -> hiB/loB (counter target 26)
    gemm_v11<<<2 * M13_T, 256, SMSZ>>>(hiA, loA,
        Whi + 0 * WOFF, Wlo + 0 * WOFF, C,
        Whi + 0 * WOFF, Wlo + 0 * WOFF, C, 2 * M13_T,
        1, 26, b2, hiB, loB);

    // Layer 3: 1-D fused GEMM + combine -> hiA/loA (counter target 52)
    gemm_v11<<<2 * M13_T, 256, SMSZ>>>(hiB, loB,
        Whi + 1 * WOFF, Wlo + 1 * WOFF, C,
        Whi + 1 * WOFF, Wlo + 1 * WOFF, C, 2 * M13_T,
        1, 52, b3, hiA, loA);

    // Merged heads: PDE (13ch -> C) + data (3ch -> Cd), 2-D grid, no fuse
    gemm_v11<<<dim3(M13_T + M3_T, 2), 256, SMSZ>>>(hiA, loA,
        Whi + 2 * WOFF, Wlo + 2 * WOFF, C,
        Whi + 3 * WOFF, Wlo + 3 * WOFF, Cd, M13_T,
        0, 0, b2, hiB, loB);

    // Merged reductions (+ counter reset for next graph replay)
    head_reduce<<<2 * (NPTS / 8), 256>>>(C, Cd, bp1, Wp2, lam1, lam2,
                                         bd1, Wd2, bd2, out);
}

// round 12
// speedup vs baseline: 1.0442x; 1.0442x over previous
#include <cuda_runtime.h>
#include <cuda_bf16.h>
#include <cstdint>

#define NPTS 65536
#define HID  256
#define SLICE ((size_t)NPTS * HID)
#define NCH  13
#define HG   256                 // sample groups (of 128) per half
#define HALF 32768               // samples per half

// fp32 GEMM-output buffers and bf16 hi/lo split activation buffers
static __device__ float          g_C  [(size_t)NCH * NPTS * HID];
static __device__ float          g_Cd [(size_t)3 * NPTS * HID];
static __device__ __nv_bfloat16  g_hiA[(size_t)NCH * NPTS * HID];
static __device__ __nv_bfloat16  g_loA[(size_t)NCH * NPTS * HID];
static __device__ __nv_bfloat16  g_hiB[(size_t)NCH * NPTS * HID];
static __device__ __nv_bfloat16  g_loB[(size_t)NCH * NPTS * HID];
// weight splits: slot 0=W2, 1=W3, 2=Wp1, 3=Wd1
static __device__ __nv_bfloat16  g_Whi[4 * 256 * 256];
static __device__ __nv_bfloat16  g_Wlo[4 * 256 * 256];

// ---------------------------------------------------------------------------
__device__ __forceinline__ void store_hl(__nv_bfloat16* __restrict__ hi,
                                         __nv_bfloat16* __restrict__ lo,
                                         size_t idx, float f) {
    unsigned u = __float_as_uint(f);
    float h = __uint_as_float(u & 0xFFFF0000u);
    hi[idx] = __ushort_as_bfloat16((unsigned short)(u >> 16));
    lo[idx] = __float2bfloat16(f - h);
}

__device__ __forceinline__ __nv_bfloat16 trunc_bf(float f) {
    return __ushort_as_bfloat16((unsigned short)(__float_as_uint(f) >> 16));
}
__device__ __forceinline__ float trunc_res(float f) {
    return f - __uint_as_float(__float_as_uint(f) & 0xFFFF0000u);
}

__global__ void wconv_kernel(const float* __restrict__ w2,
                             const float* __restrict__ w3,
                             const float* __restrict__ wp1,
                             const float* __restrict__ wd1) {
    int e = blockIdx.x * blockDim.x + threadIdx.x;
    if (e >= 4 * 65536) return;
    int m = e >> 16;
    int l = e & 65535;
    const float* src = (m == 0) ? w2 : (m == 1) ? w3 : (m == 2) ? wp1 : wd1;
    store_hl(g_Whi, g_Wlo, (size_t)e, src[l]);
}

__global__ void layer1_kernel(const float* __restrict__ x,
                              const float* __restrict__ y,
                              const float* __restrict__ t,
                              const float* __restrict__ W1,
                              const float* __restrict__ b1) {
    int e = blockIdx.x * blockDim.x + threadIdx.x;
    if (e >= NPTS * HID) return;
    int n = e >> 8;
    int k = e & 255;
    float cx = W1[k * 3 + 0];
    float cy = W1[k * 3 + 1];
    float ct = W1[k * 3 + 2];
    float z = cx * x[n] + cy * y[n] + ct * t[n] + b1[k];
    float h = tanhf(z);
    float d = 1.0f - h * h;
    const size_t S = SLICE;
    store_hl(g_hiA, g_loA, e, h);
    store_hl(g_hiA, g_loA, S * 1 + e, d * cx);
    store_hl(g_hiA, g_loA, S * 2 + e, d * cy);
    store_hl(g_hiA, g_loA, S * 3 + e, d * ct);
    float m2 = -2.0f * h * d;
    store_hl(g_hiA, g_loA, S * 4 + e, m2 * cx * cx);
    store_hl(g_hiA, g_loA, S * 5 + e, m2 * cx * cy);
    store_hl(g_hiA, g_loA, S * 6 + e, m2 * cy * cy);
    store_hl(g_hiA, g_loA, S * 7 + e, m2 * cx * ct);
    store_hl(g_hiA, g_loA, S * 8 + e, m2 * cy * ct);
    float m3 = d * (6.0f * h * h - 2.0f);
    store_hl(g_hiA, g_loA, S * 9 + e,  m3 * cx * cx * cx);
    store_hl(g_hiA, g_loA, S * 10 + e, m3 * cx * cx * cy);
    store_hl(g_hiA, g_loA, S * 11 + e, m3 * cx * cy * cy);
    store_hl(g_hiA, g_loA, S * 12 + e, m3 * cy * cy * cy);
}

// ---------------------------------------------------------------------------
// Heterogeneous "mega" kernel: blocks [0, ngemm) run the tensor-core GEMM
// (R8 loop: 128x128 tile, 8 warps, 3-stage cp.async ring, XOR swizzle,
//  Ah*Wh + Ah*Wl + Al*Wh); blocks [ngemm, ngemm+ncomb) run the vectorized
// tanh-jet combine; blocks [ngemm+ncomb, +nhr) run head reductions.
// All jobs in one launch are INDEPENDENT (software-pipelined sample halves).
// GEMM block map: g = bx; bxx = g>>1 (row tile), blockN = (g&1)*128 so both
// N-halves of a row are adjacent (L2 A reuse). bxx < nbig: job1 (W1_/C1_),
// else job2 (W2_/C2_). Row = ch*NPTS + hoffG + sg*128, ch = bxx/HG, sg = bxx%HG.
// ---------------------------------------------------------------------------
#define STGB  32768            // per-stage bytes: A 16K + W 16K
#define SMSZ  (3 * STGB)       // 98304

#define LDSM4(R, addr) \
    asm volatile("ldmatrix.sync.aligned.m8n8.x4.shared.b16 {%0,%1,%2,%3}, [%4];" \
                 : "=r"((R)[0]), "=r"((R)[1]), "=r"((R)[2]), "=r"((R)[3]) \
                 : "r"(addr))
#define CPA(dst, src) \
    asm volatile("cp.async.cg.shared.global [%0], [%1], 16;" :: "r"(dst), "l"(src))
#define CPC() asm volatile("cp.async.commit_group;")
#define CPW1() asm volatile("cp.async.wait_group 1;" ::: "memory")
#define CPW0() asm volatile("cp.async.wait_group 0;" ::: "memory")

__device__ __forceinline__ void mma_bf16(float* c, const unsigned* a,
                                         unsigned b0, unsigned b1) {
    asm volatile(
        "mma.sync.aligned.m16n8k16.row.col.f32.bf16.bf16.f32 "
        "{%0,%1,%2,%3}, {%4,%5,%6,%7}, {%8,%9}, {%0,%1,%2,%3};"
        : "+f"(c[0]), "+f"(c[1]), "+f"(c[2]), "+f"(c[3])
        : "r"(a[0]), "r"(a[1]), "r"(a[2]), "r"(a[3]), "r"(b0), "r"(b1));
}

__global__ void __launch_bounds__(256, 2)
mega(const __nv_bfloat16* __restrict__ Ahi,
     const __nv_bfloat16* __restrict__ Alo,
     const __nv_bfloat16* Whi1, const __nv_bfloat16* Wlo1, float* C1,
     const __nv_bfloat16* Whi2, const __nv_bfloat16* Wlo2, float* C2,
     int ngemm, int nbig, int hoffG,
     int ncomb, const float* __restrict__ Zc, const float* __restrict__ bvec,
     __nv_bfloat16* __restrict__ hiO, __nv_bfloat16* __restrict__ loO,
     int hoffC,
     int nhr, const float* __restrict__ Zh, const float* __restrict__ Zd,
     const float* __restrict__ bp1, const float* __restrict__ Wp2,
     const float* __restrict__ lam1p, const float* __restrict__ lam2p,
     const float* __restrict__ bd1, const float* __restrict__ Wd2,
     const float* __restrict__ bd2, float* __restrict__ out, int hoffH) {
    const int b   = blockIdx.x;
    const int tid = threadIdx.x;

    if (b < ngemm) {
        // ===================== GEMM path =====================
        extern __shared__ __align__(128) unsigned char sm[];
        const unsigned sb = (unsigned)__cvta_generic_to_shared(sm);

        int bxx = b >> 1;
        const int blockN = (b & 1) * 128;
        const __nv_bfloat16* Whi = Whi1;
        const __nv_bfloat16* Wlo = Wlo1;
        float* C = C1;
        if (bxx >= nbig) {
            bxx -= nbig;
            Whi = Whi2; Wlo = Wlo2; C = C2;
        }
        const int ch = bxx / HG;
        const int sg = bxx - ch * HG;
        const size_t blockRow = (size_t)ch * NPTS + (size_t)hoffG + (size_t)sg * 128;

        const int lane = tid & 31;
        const int warp = tid >> 5;
        const int wm   = (warp & 3) * 32;
        const int wn   = (warp >> 2) * 64;

        const int lr = tid >> 1;
        const int lc = (tid & 1) * 2;
        const unsigned sw = (unsigned)(lr & 7);
        const __nv_bfloat16* gAh = Ahi + (blockRow + lr) * 256;
        const __nv_bfloat16* gAl = Alo + (blockRow + lr) * 256;
        const __nv_bfloat16* gWh = Whi + (size_t)(blockN + lr) * 256;
        const __nv_bfloat16* gWl = Wlo + (size_t)(blockN + lr) * 256;
        const unsigned aDst = sb + lr * 128;
        const unsigned wDst = sb + 16384 + lr * 128;

        float acc[2][8][4];
#pragma unroll
        for (int i = 0; i < 2; i++)
#pragma unroll
            for (int j = 0; j < 8; j++)
#pragma unroll
                for (int l = 0; l < 4; l++) acc[i][j][l] = 0.0f;

#define ISSUE(kc) do {                                                         \
        const int _s = (kc) % 3;                                               \
        const int _ko = (kc) * 32;                                             \
        unsigned _a = aDst + _s * STGB;                                        \
        unsigned _w = wDst + _s * STGB;                                        \
        CPA(_a + ((unsigned)((lc    ) ^ sw) << 4), gAh + _ko + lc * 8);        \
        CPA(_a + ((unsigned)((lc + 1) ^ sw) << 4), gAh + _ko + lc * 8 + 8);    \
        CPA(_a + ((unsigned)((lc + 4) ^ sw) << 4), gAl + _ko + lc * 8);        \
        CPA(_a + ((unsigned)((lc + 5) ^ sw) << 4), gAl + _ko + lc * 8 + 8);    \
        CPA(_w + ((unsigned)((lc    ) ^ sw) << 4), gWh + _ko + lc * 8);        \
        CPA(_w + ((unsigned)((lc + 1) ^ sw) << 4), gWh + _ko + lc * 8 + 8);    \
        CPA(_w + ((unsigned)((lc + 4) ^ sw) << 4), gWl + _ko + lc * 8);        \
        CPA(_w + ((unsigned)((lc + 5) ^ sw) << 4), gWl + _ko + lc * 8 + 8);    \
        CPC();                                                                 \
    } while (0)

        ISSUE(0);
        ISSUE(1);

        const int arow  = wm + (lane & 15);
        const int acsel = lane >> 4;
        const int brow  = wn + (lane & 7) + ((lane >> 4) << 3);
        const int bcsel = (lane >> 3) & 1;

#pragma unroll 1
        for (int kc = 0; kc < 8; kc++) {
            if (kc < 7) { CPW1(); } else { CPW0(); }
            __syncthreads();
            if (kc < 6) ISSUE(kc + 2);

            const unsigned s0 = sb + (kc % 3) * STGB;
#pragma unroll
            for (int step = 0; step < 2; step++) {
                unsigned aH[2][4], aL[2][4];
                const int cA = step * 2 + acsel;
#pragma unroll
                for (int mt = 0; mt < 2; mt++) {
                    const int row = arow + mt * 16;
                    const unsigned rs = (unsigned)(row & 7);
                    const unsigned ab = s0 + row * 128;
                    LDSM4(aH[mt], ab + ((unsigned)(cA ^ rs) << 4));
                    LDSM4(aL[mt], ab + ((unsigned)((cA + 4) ^ rs) << 4));
                }
                const int cB = step * 2 + bcsel;
#pragma unroll
                for (int ng = 0; ng < 4; ng++) {
                    const int rowb = brow + ng * 16;
                    const unsigned rbs = (unsigned)(rowb & 7);
                    const unsigned bb = s0 + 16384 + rowb * 128;
                    unsigned bh[4], bl[4];
                    LDSM4(bh, bb + ((unsigned)(cB ^ rbs) << 4));
                    LDSM4(bl, bb + ((unsigned)((cB + 4) ^ rbs) << 4));
#pragma unroll
                    for (int mt = 0; mt < 2; mt++) {
                        mma_bf16(acc[mt][2 * ng],     aH[mt], bh[0], bh[1]);
                        mma_bf16(acc[mt][2 * ng],     aH[mt], bl[0], bl[1]);
                        mma_bf16(acc[mt][2 * ng],     aL[mt], bh[0], bh[1]);
                        mma_bf16(acc[mt][2 * ng + 1], aH[mt], bh[2], bh[3]);
                        mma_bf16(acc[mt][2 * ng + 1], aH[mt], bl[2], bl[3]);
                        mma_bf16(acc[mt][2 * ng + 1], aL[mt], bh[2], bh[3]);
                    }
                }
            }
        }

        const int g  = lane >> 2;
        const int t4 = lane & 3;
#pragma unroll
        for (int mt = 0; mt < 2; mt++) {
            size_t row = blockRow + wm + mt * 16 + g;
#pragma unroll
            for (int nt = 0; nt < 8; nt++) {
                int col = blockN + wn + nt * 8 + t4 * 2;
                *(float2*)(C + row * 256 + col) =
                    make_float2(acc[mt][nt][0], acc[mt][nt][1]);
                *(float2*)(C + (row + 8) * 256 + col) =
                    make_float2(acc[mt][nt][2], acc[mt][nt][3]);
            }
        }
        return;
    }

    if (b < ngemm + ncomb) {
        // ===================== combine path (vectorized) =====================
        const int cb = b - ngemm;
        const size_t e4 = (size_t)hoffC * 64 + (size_t)cb * 256 + tid;
        const int kb = ((int)(e4 & 63)) * 4;
        const size_t S4 = SLICE / 4;

        float4 zq[13];
#pragma unroll
        for (int ch = 0; ch < 13; ch++)
            zq[ch] = ((const float4*)Zc)[ch * S4 + e4];

        float o[13][4];
#pragma unroll
        for (int jj = 0; jj < 4; jj++) {
            float zh = ((const float*)&zq[0])[jj] + bvec[kb + jj];
            float zx = ((const float*)&zq[1])[jj],  zy = ((const float*)&zq[2])[jj];
            float zt = ((const float*)&zq[3])[jj];
            float zxx = ((const float*)&zq[4])[jj], zxy = ((const float*)&zq[5])[jj];
            float zyy = ((const float*)&zq[6])[jj], zxt = ((const float*)&zq[7])[jj];
            float zyt = ((const float*)&zq[8])[jj];
            float zxxx = ((const float*)&zq[9])[jj],  zxxy = ((const float*)&zq[10])[jj];
            float zxyy = ((const float*)&zq[11])[jj], zyyy = ((const float*)&zq[12])[jj];

            float h = tanhf(zh);
            float d = 1.0f - h * h;
            float hd2 = -2.0f * h * d;
            float c3 = (4.0f * h * h - 2.0f * d) * d;

            o[0][jj] = h;
            o[1][jj] = d * zx;
            o[2][jj] = d * zy;
            o[3][jj] = d * zt;
            o[4][jj] = d * zxx + hd2 * zx * zx;
            o[5][jj] = d * zxy + hd2 * zx * zy;
            o[6][jj] = d * zyy + hd2 * zy * zy;
            o[7][jj] = d * zxt + hd2 * zx * zt;
            o[8][jj] = d * zyt + hd2 * zy * zt;
            o[9][jj]  = d * zxxx + hd2 * 3.0f * zx * zxx + c3 * zx * zx * zx;
            o[10][jj] = d * zxxy + hd2 * (zy * zxx + 2.0f * zx * zxy) + c3 * zx * zx * zy;
            o[11][jj] = d * zxyy + hd2 * (2.0f * zy * zxy + zx * zyy) + c3 * zx * zy * zy;
            o[12][jj] = d * zyyy + hd2 * 3.0f * zy * zyy + c3 * zy * zy * zy;
        }

#pragma unroll
        for (int ch = 0; ch < 13; ch++) {
            __nv_bfloat162 h0, h1, l0, l1;
            h0.x = trunc_bf(o[ch][0]); h0.y = trunc_bf(o[ch][1]);
            h1.x = trunc_bf(o[ch][2]); h1.y = trunc_bf(o[ch][3]);
            l0.x = __float2bfloat16(trunc_res(o[ch][0]));
            l0.y = __float2bfloat16(trunc_res(o[ch][1]));
            l1.x = __float2bfloat16(trunc_res(o[ch][2]));
            l1.y = __float2bfloat16(trunc_res(o[ch][3]));
            ((__nv_bfloat162*)hiO)[ch * (S4 * 2) + e4 * 2]     = h0;
            ((__nv_bfloat162*)hiO)[ch * (S4 * 2) + e4 * 2 + 1] = h1;
            ((__nv_bfloat162*)loO)[ch * (S4 * 2) + e4 * 2]     = l0;
            ((__nv_bfloat162*)loO)[ch * (S4 * 2) + e4 * 2 + 1] = l1;
        }
        return;
    }

    // ===================== head_reduce path =====================
    {
        const int hb = b - ngemm - ncomb;      // 0 .. nhr-1
        const int lane = tid & 31;
        const int w = tid >> 5;
        const size_t S = SLICE;
        const int NHB = 4096;                  // PDE blocks per half

        if (hb < NHB) {
            const int samp = hoffH + hb * 8 + w;
            const size_t base = (size_t)samp * 256;

            float acc[14];
#pragma unroll
            for (int i = 0; i < 14; i++) acc[i] = 0.0f;

#pragma unroll
            for (int kk = lane; kk < 256; kk += 32) {
                size_t e = base + kk;
                float zh = Zh[e] + bp1[kk];
                float h = tanhf(zh);
                float d = 1.0f - h * h;
                float zx = Zh[S + e], zy = Zh[2 * S + e], zt = Zh[3 * S + e];
                float zxx = Zh[4 * S + e], zxy = Zh[5 * S + e], zyy = Zh[6 * S + e];
                float zxt = Zh[7 * S + e], zyt = Zh[8 * S + e];
                float zxxx = Zh[9 * S + e], zxxy = Zh[10 * S + e];
                float zxyy = Zh[11 * S + e], zyyy = Zh[12 * S + e];
                float hd2 = -2.0f * h * d;
                float c3 = (4.0f * h * h - 2.0f * d) * d;

                float hx = d * zx, hy = d * zy, ht = d * zt;
                float hxx = d * zxx + hd2 * zx * zx;
                float hxy = d * zxy + hd2 * zx * zy;
                float hyy = d * zyy + hd2 * zy * zy;
                float hxt = d * zxt + hd2 * zx * zt;
                float hyt = d * zyt + hd2 * zy * zt;
                float hxxx = d * zxxx + hd2 * 3.0f * zx * zxx + c3 * zx * zx * zx;
                float hxxy = d * zxxy + hd2 * (zy * zxx + 2.0f * zx * zxy) + c3 * zx * zx * zy;
                float hxyy = d * zxyy + hd2 * (2.0f * zy * zxy + zx * zyy) + c3 * zx * zy * zy;
                float hyyy = d * zyyy + hd2 * 3.0f * zy * zyy + c3 * zy * zy * zy;

                float w0 = Wp2[kk];
                float w1 = Wp2[256 + kk];
                acc[0] += w0 * hx;   acc[1] += w0 * hy;   acc[2] += w0 * ht;
                acc[3] += w0 * hxx;  acc[4] += w0 * hxy;  acc[5] += w0 * hyy;
                acc[6] += w0 * hxt;  acc[7] += w0 * hyt;
                acc[8] += w0 * hxxx; acc[9] += w0 * hxxy;
                acc[10] += w0 * hxyy; acc[11] += w0 * hyyy;
                acc[12] += w1 * hx;  acc[13] += w1 * hy;
            }
#pragma unroll
            for (int i = 0; i < 14; i++)
#pragma unroll
                for (int o = 16; o; o >>= 1)
                    acc[i] += __shfl_xor_sync(0xffffffffu, acc[i], o);

            if (lane == 0) {
                float lam1 = lam1p[0], lam2 = lam2p[0];
                float sx = acc[0], sy = acc[1];
                float sxx = acc[3], sxy = acc[4], syy = acc[5], sxt = acc[6], syt = acc[7];
                float sxxx = acc[8], sxxy = acc[9], sxyy = acc[10], syyy = acc[11];
                float px = acc[12], py = acc[13];
                float u = sy, v = -sx;
                float f = lam1 * (syt + u * sxy + v * syy) + px - lam2 * (sxxy + syyy);
                float g2 = lam1 * (-sxt + u * (-sxx) + v * (-sxy)) + py - lam2 * (-sxxx - sxyy);
                out[3 * NPTS + samp] = f;
                out[4 * NPTS + samp] = g2;
            }
        } else {
            const int samp = hoffH + (hb - NHB) * 8 + w;
            const size_t base = (size_t)samp * 256;
            float ap = 0.0f, au = 0.0f, av = 0.0f;
#pragma unroll
            for (int kk = lane; kk < 256; kk += 32) {
                size_t e = base + kk;
                float zh = Zd[e] + bd1[kk];
                float h = tanhf(zh);
                float d = 1.0f - h * h;
                float hx = d * Zd[S + e];
                float hy = d * Zd[2 * S + e];
                float w0 = Wd2[kk];
                float w1 = Wd2[256 + kk];
                ap += w1 * h;
                au += w0 * hy;
                av += w0 * hx;
            }
#pragma unroll
            for (int o = 16; o; o >>= 1) {
                ap += __shfl_xor_sync(0xffffffffu, ap, o);
                au += __shfl_xor_sync(0xffffffffu, au, o);
                av += __shfl_xor_sync(0xffffffffu, av, o);
            }
            if (lane == 0) {
                out[samp] = ap + bd2[1];
                out[NPTS + samp] = au;
                out[2 * NPTS + samp] = -av;
            }
        }
    }
}

// ---------------------------------------------------------------------------
// Host launch: software-pipelined halves, independent work co-scheduled.
// ---------------------------------------------------------------------------
extern "C" void kernel_launch(void* const* d_in, const int* in_sizes, int n_in,
                              void* d_out, int out_size) {
    const float* x   = (const float*)d_in[0];
    const float* y   = (const float*)d_in[1];
    const float* t   = (const float*)d_in[2];
    const float* W1  = (const float*)d_in[6];
    const float* b1  = (const float*)d_in[7];
    const float* W2  = (const float*)d_in[8];
    const float* b2  = (const float*)d_in[9];
    const float* W3  = (const float*)d_in[10];
    const float* b3  = (const float*)d_in[11];
    const float* Wp1 = (const float*)d_in[12];
    const float* bp1 = (const float*)d_in[13];
    const float* Wp2 = (const float*)d_in[14];
    const float* Wd1 = (const float*)d_in[16];
    const float* bd1 = (const float*)d_in[17];
    const float* Wd2 = (const float*)d_in[18];
    const float* bd2 = (const float*)d_in[19];
    const float* lam1 = (const float*)d_in[20];
    const float* lam2 = (const float*)d_in[21];
    float* out = (float*)d_out;

    float *C = nullptr, *Cd = nullptr;
    __nv_bfloat16 *hiA, *loA, *hiB, *loB, *Whi, *Wlo;
    cudaGetSymbolAddress((void**)&C,   g_C);
    cudaGetSymbolAddress((void**)&Cd,  g_Cd);
    cudaGetSymbolAddress((void**)&hiA, g_hiA);
    cudaGetSymbolAddress((void**)&loA, g_loA);
    cudaGetSymbolAddress((void**)&hiB, g_hiB);
    cudaGetSymbolAddress((void**)&loB, g_loB);
    cudaGetSymbolAddress((void**)&Whi, g_Whi);
    cudaGetSymbolAddress((void**)&Wlo, g_Wlo);

    static bool attr_set = false;
    if (!attr_set) {
        cudaFuncSetAttribute(mega, cudaFuncAttributeMaxDynamicSharedMemorySize, SMSZ);
        attr_set = true;
    }

    const int NH = NPTS * HID;
    const int WOFF = 256 * 256;
    const int GL  = 2 * 13 * HG;       // 6656 gemm blocks per layer-half
    const int GH  = 2 * 16 * HG;       // 8192 gemm blocks per heads-half
    const int NCB = 8192;              // combine blocks per half
    const int NHR = 8192;              // head_reduce blocks per half
    const int NBIG = 13 * HG;          // 3328 (row-tile threshold for heads)

    wconv_kernel<<<(4 * 65536) / 256, 256>>>(W2, W3, Wp1, Wd1);
    layer1_kernel<<<NH / 256, 256>>>(x, y, t, W1, b1);

    // G2a: layer-2 GEMM, half 0
    mega<<<GL, 256, SMSZ>>>(hiA, loA,
        Whi + 0 * WOFF, Wlo + 0 * WOFF, C,  Whi, Wlo, C,  GL, NBIG, 0,
        0, C, b2, hiB, loB, 0,
        0, C, Cd, bp1, Wp2, lam1, lam2, bd1, Wd2, bd2, out, 0);

    // M1: G2b + C2a
    mega<<<GL + NCB, 256, SMSZ>>>(hiA, loA,
        Whi + 0 * WOFF, Wlo + 0 * WOFF, C,  Whi, Wlo, C,  GL, NBIG, HALF,
        NCB, C, b2, hiB, loB, 0,
        0, C, Cd, bp1, Wp2, lam1, lam2, bd1, Wd2, bd2, out, 0);

    // M2: G3a + C2b
    mega<<<GL + NCB, 256, SMSZ>>>(hiB, loB,
        Whi + 1 * WOFF, Wlo + 1 * WOFF, C,  Whi, Wlo, C,  GL, NBIG, 0,
        NCB, C, b2, hiB, loB, HALF,
        0, C, Cd, bp1, Wp2, lam1, lam2, bd1, Wd2, bd2, out, 0);

    // M3: G3b + C3a
    mega<<<GL + NCB, 256, SMSZ>>>(hiB, loB,
        Whi + 1 * WOFF, Wlo + 1 * WOFF, C,  Whi, Wlo, C,  GL, NBIG, HALF,
        NCB, C, b3, hiA, loA, 0,
        0, C, Cd, bp1, Wp2, lam1, lam2, bd1, Wd2, bd2, out, 0);

    // M4: Ha (PDE 13ch -> C, data 3ch -> Cd; half 0) + C3b
    mega<<<GH + NCB, 256, SMSZ>>>(hiA, loA,
        Whi + 2 * WOFF, Wlo + 2 * WOFF, C,
        Whi + 3 * WOFF, Wlo + 3 * WOFF, Cd,  GH, NBIG, 0,
        NCB, C, b3, hiA, loA, HALF,
        0, C, Cd, bp1, Wp2, lam1, lam2, bd1, Wd2, bd2, out, 0);

    // M5: Hb + HRa
    mega<<<GH + NHR, 256, SMSZ>>>(hiA, loA,
        Whi + 2 * WOFF, Wlo + 2 * WOFF, C,
        Whi + 3 * WOFF, Wlo + 3 * WOFF, Cd,  GH, NBIG, HALF,
        0, C, b3, hiA, loA, 0,
        NHR, C, Cd, bp1, Wp2, lam1, lam2, bd1, Wd2, bd2, out, 0);

    // HRb
    mega<<<NHR, 256, SMSZ>>>(hiA, loA,
        Whi, Wlo, C,  Whi, Wlo, Cd,  0, NBIG, 0,
        0, C, b3, hiA, loA, 0,
        NHR, C, Cd, bp1, Wp2, lam1, lam2, bd1, Wd2, bd2, out, HALF);
}